// round 1
// baseline (speedup 1.0000x reference)
#include <cuda_runtime.h>
#include <math.h>

#define SEQ 4096
#define DIM 1024

// Scratch (allocation-free rule: device globals)
__device__ float g_q[SEQ * DIM];
__device__ float g_k[SEQ * DIM];
__device__ float g_v[SEQ * DIM];
__device__ float g_s[(size_t)SEQ * SEQ];

// ---------------------------------------------------------------------------
// Tiled SGEMM: C[M,N] = scale * A[M,K] * op(B)
//   B_IS_NT = true : B is [N,K] row-major (C = A * B^T)   -> QKV proj, Q*K^T
//   B_IS_NT = false: B is [K,N] row-major (C = A * B)     -> P*V
// BM=BN=128, BK=8, 256 threads, 8x8 accumulator per thread.
// Requires M%128==0, N%128==0, K%8==0 (holds: 4096/1024 shapes).
// ---------------------------------------------------------------------------
template <bool B_IS_NT>
__global__ __launch_bounds__(256, 2)
void gemm128(const float* __restrict__ A, const float* __restrict__ B,
             float* __restrict__ C, int M, int N, int K, float scale)
{
    constexpr int BM = 128, BN = 128, BK = 8;
    __shared__ float As[BK][BM];
    __shared__ float Bs[BK][BN];

    const int tid  = threadIdx.x;
    const int tx   = tid & 15;   // 0..15  -> col group of 8
    const int ty   = tid >> 4;   // 0..15  -> row group of 8
    const int row0 = blockIdx.y * BM;
    const int col0 = blockIdx.x * BN;

    float acc[8][8];
#pragma unroll
    for (int i = 0; i < 8; i++)
#pragma unroll
        for (int j = 0; j < 8; j++) acc[i][j] = 0.0f;

    // A-tile loading: 128 rows x 8 k-cols = 256 float4 (2 per row)
    const int arow = tid >> 1;        // 0..127
    const int apos = (tid & 1) * 4;   // 0 or 4
    const float* Aptr = A + (size_t)(row0 + arow) * K + apos;

    // B-tile loading
    const float* Bptr;
    int bk_ld = 0, bn_ld = 0;
    if (B_IS_NT) {
        // B[N,K]: same pattern as A (rows = output cols)
        Bptr = B + (size_t)(col0 + arow) * K + apos;
    } else {
        // B[K,N]: 8 k-rows x 128 n-cols = 256 float4 (32 per row)
        bk_ld = tid >> 5;            // 0..7
        bn_ld = (tid & 31) * 4;      // 0..124
        Bptr  = B + (size_t)bk_ld * N + col0 + bn_ld;
    }

    for (int k0 = 0; k0 < K; k0 += BK) {
        float4 av = *(const float4*)Aptr;
        Aptr += BK;
        As[apos + 0][arow] = av.x;
        As[apos + 1][arow] = av.y;
        As[apos + 2][arow] = av.z;
        As[apos + 3][arow] = av.w;

        if (B_IS_NT) {
            float4 bv = *(const float4*)Bptr;
            Bptr += BK;
            Bs[apos + 0][arow] = bv.x;
            Bs[apos + 1][arow] = bv.y;
            Bs[apos + 2][arow] = bv.z;
            Bs[apos + 3][arow] = bv.w;
        } else {
            float4 bv = *(const float4*)Bptr;
            Bptr += (size_t)BK * N;
            Bs[bk_ld][bn_ld + 0] = bv.x;
            Bs[bk_ld][bn_ld + 1] = bv.y;
            Bs[bk_ld][bn_ld + 2] = bv.z;
            Bs[bk_ld][bn_ld + 3] = bv.w;
        }
        __syncthreads();

#pragma unroll
        for (int k = 0; k < BK; k++) {
            float4 a0 = *(const float4*)&As[k][ty * 8];
            float4 a1 = *(const float4*)&As[k][ty * 8 + 4];
            float4 b0 = *(const float4*)&Bs[k][tx * 8];
            float4 b1 = *(const float4*)&Bs[k][tx * 8 + 4];
            float ra[8] = {a0.x, a0.y, a0.z, a0.w, a1.x, a1.y, a1.z, a1.w};
            float rb[8] = {b0.x, b0.y, b0.z, b0.w, b1.x, b1.y, b1.z, b1.w};
#pragma unroll
            for (int i = 0; i < 8; i++)
#pragma unroll
                for (int j = 0; j < 8; j++)
                    acc[i][j] = fmaf(ra[i], rb[j], acc[i][j]);
        }
        __syncthreads();
    }

#pragma unroll
    for (int i = 0; i < 8; i++) {
        float* Crow = C + (size_t)(row0 + ty * 8 + i) * N + col0 + tx * 8;
        float4 o0 = make_float4(acc[i][0] * scale, acc[i][1] * scale,
                                acc[i][2] * scale, acc[i][3] * scale);
        float4 o1 = make_float4(acc[i][4] * scale, acc[i][5] * scale,
                                acc[i][6] * scale, acc[i][7] * scale);
        *(float4*)Crow       = o0;
        *(float4*)(Crow + 4) = o1;
    }
}

// ---------------------------------------------------------------------------
// Row softmax over S[SEQ, N]; one block per row, row staged in shared memory.
// ---------------------------------------------------------------------------
__global__ __launch_bounds__(256)
void softmax_rows(float* __restrict__ S, int N)
{
    __shared__ float buf[SEQ];
    __shared__ float red[32];
    const int tid   = threadIdx.x;
    const int lane  = tid & 31;
    const int warp  = tid >> 5;
    const int nwarp = blockDim.x >> 5;
    float* row = S + (size_t)blockIdx.x * N;

    // pass 1: load + max
    float lmax = -1e30f;
    for (int i = tid; i < N; i += blockDim.x) {
        float v = row[i];
        buf[i] = v;
        lmax = fmaxf(lmax, v);
    }
#pragma unroll
    for (int o = 16; o > 0; o >>= 1)
        lmax = fmaxf(lmax, __shfl_xor_sync(0xffffffffu, lmax, o));
    if (lane == 0) red[warp] = lmax;
    __syncthreads();
    if (tid < 32) {
        float v = (tid < nwarp) ? red[tid] : -1e30f;
#pragma unroll
        for (int o = 16; o > 0; o >>= 1)
            v = fmaxf(v, __shfl_xor_sync(0xffffffffu, v, o));
        red[tid] = v;
    }
    __syncthreads();
    const float rmax = red[0];
    __syncthreads();   // protect red[] before reuse for the sum

    // pass 2: exp + sum
    float lsum = 0.0f;
    for (int i = tid; i < N; i += blockDim.x) {
        float e = __expf(buf[i] - rmax);
        buf[i] = e;
        lsum += e;
    }
#pragma unroll
    for (int o = 16; o > 0; o >>= 1)
        lsum += __shfl_xor_sync(0xffffffffu, lsum, o);
    if (lane == 0) red[warp] = lsum;
    __syncthreads();
    if (tid < 32) {
        float v = (tid < nwarp) ? red[tid] : 0.0f;
#pragma unroll
        for (int o = 16; o > 0; o >>= 1)
            v += __shfl_xor_sync(0xffffffffu, v, o);
        red[tid] = v;
    }
    __syncthreads();
    const float inv = 1.0f / red[0];

    // pass 3: normalize + store
    for (int i = tid; i < N; i += blockDim.x)
        row[i] = buf[i] * inv;
}

// ---------------------------------------------------------------------------
extern "C" void kernel_launch(void* const* d_in, const int* in_sizes, int n_in,
                              void* d_out, int out_size)
{
    const float* x  = (const float*)d_in[0];
    const float* Wq = (const float*)d_in[1];
    const float* Wk = (const float*)d_in[2];
    const float* Wv = (const float*)d_in[3];
    float* out = (float*)d_out;

    float *qp, *kp, *vp, *sp;
    cudaGetSymbolAddress((void**)&qp, g_q);
    cudaGetSymbolAddress((void**)&kp, g_k);
    cudaGetSymbolAddress((void**)&vp, g_v);
    cudaGetSymbolAddress((void**)&sp, g_s);

    const float scale = 1.0f / 32.0f;  // 1/sqrt(1024)

    dim3 gProj(DIM / 128, SEQ / 128);  // (8, 32)
    gemm128<true><<<gProj, 256>>>(x, Wq, qp, SEQ, DIM, DIM, 1.0f);
    gemm128<true><<<gProj, 256>>>(x, Wk, kp, SEQ, DIM, DIM, 1.0f);
    gemm128<true><<<gProj, 256>>>(x, Wv, vp, SEQ, DIM, DIM, 1.0f);

    dim3 gScore(SEQ / 128, SEQ / 128); // (32, 32)
    gemm128<true><<<gScore, 256>>>(qp, kp, sp, SEQ, SEQ, DIM, scale);

    softmax_rows<<<SEQ, 256>>>(sp, SEQ);

    gemm128<false><<<gProj, 256>>>(sp, vp, out, SEQ, DIM, SEQ, 1.0f);
}

// round 3
// speedup vs baseline: 3.1627x; 3.1627x over previous
#include <cuda_runtime.h>
#include <cstdint>
#include <math.h>

#define SEQ 4096
#define DIM 1024

// Scratch (allocation-free rule: device globals)
__device__ float g_q[SEQ * DIM];
__device__ float g_k[SEQ * DIM];
__device__ float g_v[SEQ * DIM];          // holds V^T [DIM, SEQ]
__device__ float g_s[(size_t)SEQ * SEQ];

// ---------------------------------------------------------------------------
// PTX helpers (base-target-safe: cp.async + mma.sync only)
// ---------------------------------------------------------------------------
__device__ __forceinline__ uint32_t smem_u32(const void* p) {
    uint32_t a;
    asm("{ .reg .u64 t; cvta.to.shared.u64 t, %1; cvt.u32.u64 %0, t; }" : "=r"(a) : "l"(p));
    return a;
}
__device__ __forceinline__ void cp16(uint32_t s, const void* g) {
    asm volatile("cp.async.cg.shared.global [%0], [%1], 16;" :: "r"(s), "l"(g));
}
__device__ __forceinline__ void cp_commit() {
    asm volatile("cp.async.commit_group;" ::: "memory");
}
__device__ __forceinline__ uint32_t f2tf32(float x) {
    uint32_t y;
    asm("cvt.rna.tf32.f32 %0, %1;" : "=r"(y) : "f"(x));
    return y;
}
__device__ __forceinline__ void mma_tf32(float* c, const uint32_t* a, const uint32_t* b) {
    asm volatile(
        "mma.sync.aligned.m16n8k8.row.col.f32.tf32.tf32.f32 "
        "{%0,%1,%2,%3}, {%4,%5,%6,%7}, {%8,%9}, {%0,%1,%2,%3};"
        : "+f"(c[0]), "+f"(c[1]), "+f"(c[2]), "+f"(c[3])
        : "r"(a[0]), "r"(a[1]), "r"(a[2]), "r"(a[3]), "r"(b[0]), "r"(b[1]));
}

// ---------------------------------------------------------------------------
// tf32 mma.sync NT GEMM: C[M,N] = scale * A[M,K] * B^T,  B stored [N,K] row-major.
// BM=BN=128, BK=16, 3-stage cp.async, 256 threads, 8 warps (2x4), 64x32/warp.
// Requires M%128==0, N%128==0, K%16==0.
// ---------------------------------------------------------------------------
#define SW 20                      // smem words per 16-float row (conflict-free)
#define TILE_W (128 * SW)          // words per A (or B) tile
#define NSTG 3
#define SMEM_BYTES (NSTG * 2 * TILE_W * 4)   // 61440

__global__ __launch_bounds__(256, 2)
void gemm_mma(const float* __restrict__ A, const float* __restrict__ B,
              float* __restrict__ C, int M, int N, int K, float scale)
{
    extern __shared__ float sm[];
    const int tid  = threadIdx.x;
    const int lane = tid & 31;
    const int wid  = tid >> 5;
    const int gid  = lane >> 2;    // 0..7
    const int tig  = lane & 3;     // 0..3
    const int wm   = (wid & 1) * 64;
    const int wn   = (wid >> 1) * 32;
    const int row0 = blockIdx.y * 128;
    const int col0 = blockIdx.x * 128;

    // cp.async pattern: each thread covers rows r_ld, r_ld+64 of A and B (16B each)
    const int r_ld = tid >> 2;            // 0..63
    const int g_ld = (tid & 3) * 4;       // k-offset (floats)
    const uint32_t sm0 = smem_u32(sm);

    float acc[4][4][4];
#pragma unroll
    for (int i = 0; i < 4; i++)
#pragma unroll
        for (int j = 0; j < 4; j++)
#pragma unroll
            for (int q = 0; q < 4; q++) acc[i][j][q] = 0.0f;

    const int KT = K >> 4;   // K / 16

    auto issue = [&](int slot, int kt) {
        const uint32_t sa = sm0 + (slot * 2 * TILE_W) * 4;
        const uint32_t sb = sa + TILE_W * 4;
        const float* ga = A + (size_t)(row0 + r_ld) * K + kt * 16 + g_ld;
        const float* gb = B + (size_t)(col0 + r_ld) * K + kt * 16 + g_ld;
        cp16(sa + (r_ld * SW + g_ld) * 4, ga);
        cp16(sa + ((r_ld + 64) * SW + g_ld) * 4, ga + (size_t)64 * K);
        cp16(sb + (r_ld * SW + g_ld) * 4, gb);
        cp16(sb + ((r_ld + 64) * SW + g_ld) * 4, gb + (size_t)64 * K);
    };

    // prologue: 2 stages in flight
    issue(0, 0); cp_commit();
    issue(1, 1); cp_commit();

    for (int kt = 0; kt < KT; kt++) {
        if (kt + 2 < KT) issue((kt + 2) % NSTG, kt + 2);
        cp_commit();                                    // uniform group count
        asm volatile("cp.async.wait_group 2;" ::: "memory");
        __syncthreads();

        const float* Sa = sm + ((kt % NSTG) * 2) * TILE_W;
        const float* Sb = Sa + TILE_W;

#pragma unroll
        for (int ks = 0; ks < 2; ks++) {
            const int kw = ks * 8;
            uint32_t af[4][4], bf[4][2];
#pragma unroll
            for (int mt = 0; mt < 4; mt++) {
                const int r = wm + mt * 16 + gid;
                af[mt][0] = f2tf32(Sa[r * SW + kw + tig]);
                af[mt][1] = f2tf32(Sa[(r + 8) * SW + kw + tig]);
                af[mt][2] = f2tf32(Sa[r * SW + kw + tig + 4]);
                af[mt][3] = f2tf32(Sa[(r + 8) * SW + kw + tig + 4]);
            }
#pragma unroll
            for (int nt = 0; nt < 4; nt++) {
                const int c = wn + nt * 8 + gid;
                bf[nt][0] = f2tf32(Sb[c * SW + kw + tig]);
                bf[nt][1] = f2tf32(Sb[c * SW + kw + tig + 4]);
            }
#pragma unroll
            for (int mt = 0; mt < 4; mt++)
#pragma unroll
                for (int nt = 0; nt < 4; nt++)
                    mma_tf32(acc[mt][nt], af[mt], bf[nt]);
        }
        __syncthreads();
    }

    // Epilogue: c0/c1 at (row, 2*tig), c2/c3 at (row+8, 2*tig)
#pragma unroll
    for (int mt = 0; mt < 4; mt++) {
#pragma unroll
        for (int nt = 0; nt < 4; nt++) {
            const int r = row0 + wm + mt * 16 + gid;
            const int c = col0 + wn + nt * 8 + 2 * tig;
            float2 v0 = make_float2(acc[mt][nt][0] * scale, acc[mt][nt][1] * scale);
            float2 v1 = make_float2(acc[mt][nt][2] * scale, acc[mt][nt][3] * scale);
            *(float2*)(C + (size_t)r * N + c)       = v0;
            *(float2*)(C + (size_t)(r + 8) * N + c) = v1;
        }
    }
}

// ---------------------------------------------------------------------------
// Row softmax over S[SEQ, N]; one block per row, row staged in shared memory.
// ---------------------------------------------------------------------------
__global__ __launch_bounds__(256)
void softmax_rows(float* __restrict__ S, int N)
{
    __shared__ float buf[SEQ];
    __shared__ float red[32];
    const int tid   = threadIdx.x;
    const int lane  = tid & 31;
    const int warp  = tid >> 5;
    const int nwarp = blockDim.x >> 5;
    float* row = S + (size_t)blockIdx.x * N;

    float lmax = -1e30f;
    for (int i = tid; i < N; i += blockDim.x) {
        float v = row[i];
        buf[i] = v;
        lmax = fmaxf(lmax, v);
    }
#pragma unroll
    for (int o = 16; o > 0; o >>= 1)
        lmax = fmaxf(lmax, __shfl_xor_sync(0xffffffffu, lmax, o));
    if (lane == 0) red[warp] = lmax;
    __syncthreads();
    if (tid < 32) {
        float v = (tid < nwarp) ? red[tid] : -1e30f;
#pragma unroll
        for (int o = 16; o > 0; o >>= 1)
            v = fmaxf(v, __shfl_xor_sync(0xffffffffu, v, o));
        red[tid] = v;
    }
    __syncthreads();
    const float rmax = red[0];
    __syncthreads();

    float lsum = 0.0f;
    for (int i = tid; i < N; i += blockDim.x) {
        float e = __expf(buf[i] - rmax);
        buf[i] = e;
        lsum += e;
    }
#pragma unroll
    for (int o = 16; o > 0; o >>= 1)
        lsum += __shfl_xor_sync(0xffffffffu, lsum, o);
    if (lane == 0) red[warp] = lsum;
    __syncthreads();
    if (tid < 32) {
        float v = (tid < nwarp) ? red[tid] : 0.0f;
#pragma unroll
        for (int o = 16; o > 0; o >>= 1)
            v += __shfl_xor_sync(0xffffffffu, v, o);
        red[tid] = v;
    }
    __syncthreads();
    const float inv = 1.0f / red[0];

    for (int i = tid; i < N; i += blockDim.x)
        row[i] = buf[i] * inv;
}

// ---------------------------------------------------------------------------
extern "C" void kernel_launch(void* const* d_in, const int* in_sizes, int n_in,
                              void* d_out, int out_size)
{
    const float* x  = (const float*)d_in[0];
    const float* Wq = (const float*)d_in[1];
    const float* Wk = (const float*)d_in[2];
    const float* Wv = (const float*)d_in[3];
    float* out = (float*)d_out;

    float *qp, *kp, *vp, *sp;
    cudaGetSymbolAddress((void**)&qp, g_q);
    cudaGetSymbolAddress((void**)&kp, g_k);
    cudaGetSymbolAddress((void**)&vp, g_v);
    cudaGetSymbolAddress((void**)&sp, g_s);

    cudaFuncSetAttribute(gemm_mma, cudaFuncAttributeMaxDynamicSharedMemorySize, SMEM_BYTES);

    const float scale = 1.0f / 32.0f;  // 1/sqrt(1024)

    // Q = X @ Wq^T   [4096,1024]
    gemm_mma<<<dim3(DIM / 128, SEQ / 128), 256, SMEM_BYTES>>>(x, Wq, qp, SEQ, DIM, DIM, 1.0f);
    // K = X @ Wk^T   [4096,1024]
    gemm_mma<<<dim3(DIM / 128, SEQ / 128), 256, SMEM_BYTES>>>(x, Wk, kp, SEQ, DIM, DIM, 1.0f);
    // V^T = Wv @ X^T [1024,4096]
    gemm_mma<<<dim3(SEQ / 128, DIM / 128), 256, SMEM_BYTES>>>(Wv, x, vp, DIM, SEQ, DIM, 1.0f);
    // S = (Q @ K^T) * scale  [4096,4096]
    gemm_mma<<<dim3(SEQ / 128, SEQ / 128), 256, SMEM_BYTES>>>(qp, kp, sp, SEQ, SEQ, DIM, scale);
    // softmax rows
    softmax_rows<<<SEQ, 256>>>(sp, SEQ);
    // O = P @ V = P @ (V^T rows)  [4096,1024]
    gemm_mma<<<dim3(DIM / 128, SEQ / 128), 256, SMEM_BYTES>>>(sp, vp, out, SEQ, DIM, SEQ, 1.0f);
}

// round 4
// speedup vs baseline: 3.2788x; 1.0367x over previous
#include <cuda_runtime.h>
#include <cstdint>
#include <math.h>

#define SEQ 4096
#define DIM 1024

// Scratch (allocation-free rule: device globals)
__device__ float g_x[SEQ * DIM];          // tf32-rounded x
__device__ float g_wq[DIM * DIM];
__device__ float g_wk[DIM * DIM];
__device__ float g_wv[DIM * DIM];
__device__ float g_q[SEQ * DIM];
__device__ float g_k[SEQ * DIM];
__device__ float g_v[SEQ * DIM];          // holds V^T [DIM, SEQ]
__device__ float g_s[(size_t)SEQ * SEQ];

// ---------------------------------------------------------------------------
// PTX helpers (base-target-safe: cp.async + mma.sync only)
// ---------------------------------------------------------------------------
__device__ __forceinline__ uint32_t smem_u32(const void* p) {
    uint32_t a;
    asm("{ .reg .u64 t; cvta.to.shared.u64 t, %1; cvt.u32.u64 %0, t; }" : "=r"(a) : "l"(p));
    return a;
}
__device__ __forceinline__ void cp16(uint32_t s, const void* g) {
    asm volatile("cp.async.cg.shared.global [%0], [%1], 16;" :: "r"(s), "l"(g));
}
__device__ __forceinline__ void cp_commit() {
    asm volatile("cp.async.commit_group;" ::: "memory");
}
__device__ __forceinline__ float round_tf32f(float x) {
    uint32_t y;
    asm("cvt.rna.tf32.f32 %0, %1;" : "=r"(y) : "f"(x));
    return __uint_as_float(y);
}
__device__ __forceinline__ void mma_tf32(float* c, const uint32_t* a, const uint32_t* b) {
    asm volatile(
        "mma.sync.aligned.m16n8k8.row.col.f32.tf32.tf32.f32 "
        "{%0,%1,%2,%3}, {%4,%5,%6,%7}, {%8,%9}, {%0,%1,%2,%3};"
        : "+f"(c[0]), "+f"(c[1]), "+f"(c[2]), "+f"(c[3])
        : "r"(a[0]), "r"(a[1]), "r"(a[2]), "r"(a[3]), "r"(b[0]), "r"(b[1]));
}

// ---------------------------------------------------------------------------
// Elementwise tf32 rounding pre-pass
// ---------------------------------------------------------------------------
__global__ __launch_bounds__(256)
void round_arr(const float* __restrict__ in, float* __restrict__ out, int n4)
{
    int i = blockIdx.x * blockDim.x + threadIdx.x;
    if (i < n4) {
        float4 v = ((const float4*)in)[i];
        v.x = round_tf32f(v.x); v.y = round_tf32f(v.y);
        v.z = round_tf32f(v.z); v.w = round_tf32f(v.w);
        ((float4*)out)[i] = v;
    }
}

// ---------------------------------------------------------------------------
// tf32 mma.sync NT GEMM: C[M,N] = scale * A[M,K] * B^T,  B stored [N,K] row-major.
// Operands must be pre-rounded to tf32 (low 13 mantissa bits zero).
// BM=BN=128, BK=16, 4-stage cp.async (1 sync/iter), 256 threads, 8 warps (2x4),
// 64x32 per warp. Requires M%128==0, N%128==0, K%16==0.
// ROUND_OUT: round outputs to tf32 in the epilogue (for operands of later GEMMs).
// ---------------------------------------------------------------------------
#define SW 20                      // smem words per 16-float row (conflict-free)
#define TILE_W (128 * SW)          // words per A (or B) tile
#define NSTG 4
#define SMEM_BYTES (NSTG * 2 * TILE_W * 4)   // 81920

template <bool ROUND_OUT>
__global__ __launch_bounds__(256, 2)
void gemm_mma(const float* __restrict__ A, const float* __restrict__ B,
              float* __restrict__ C, int M, int N, int K, float scale)
{
    extern __shared__ float sm[];
    const int tid  = threadIdx.x;
    const int lane = tid & 31;
    const int wid  = tid >> 5;
    const int gid  = lane >> 2;    // 0..7
    const int tig  = lane & 3;     // 0..3
    const int wm   = (wid & 1) * 64;
    const int wn   = (wid >> 1) * 32;
    const int row0 = blockIdx.y * 128;
    const int col0 = blockIdx.x * 128;

    const int r_ld = tid >> 2;            // 0..63
    const int g_ld = (tid & 3) * 4;       // k-offset (floats)
    const uint32_t sm0 = smem_u32(sm);

    float acc[4][4][4];
#pragma unroll
    for (int i = 0; i < 4; i++)
#pragma unroll
        for (int j = 0; j < 4; j++)
#pragma unroll
            for (int q = 0; q < 4; q++) acc[i][j][q] = 0.0f;

    const int KT = K >> 4;   // K / 16

    auto issue = [&](int slot, int kt) {
        const uint32_t sa = sm0 + (slot * 2 * TILE_W) * 4;
        const uint32_t sb = sa + TILE_W * 4;
        const float* ga = A + (size_t)(row0 + r_ld) * K + kt * 16 + g_ld;
        const float* gb = B + (size_t)(col0 + r_ld) * K + kt * 16 + g_ld;
        cp16(sa + (r_ld * SW + g_ld) * 4, ga);
        cp16(sa + ((r_ld + 64) * SW + g_ld) * 4, ga + (size_t)64 * K);
        cp16(sb + (r_ld * SW + g_ld) * 4, gb);
        cp16(sb + ((r_ld + 64) * SW + g_ld) * 4, gb + (size_t)64 * K);
    };

    // prologue: 3 stages in flight
    issue(0, 0); cp_commit();
    issue(1, 1); cp_commit();
    issue(2, 2); cp_commit();

    for (int kt = 0; kt < KT; kt++) {
        asm volatile("cp.async.wait_group 2;" ::: "memory");
        __syncthreads();
        // slot (kt+3)&3 == (kt-1)&3: all warps finished computing kt-1 before
        // the sync above, so refilling it now is safe.
        if (kt + 3 < KT) issue((kt + 3) & 3, kt + 3);
        cp_commit();

        const float* Sa = sm + ((kt & 3) * 2) * TILE_W;
        const float* Sb = Sa + TILE_W;
        const float* pa = Sa + (wm + gid) * SW;   // per-warp row base
        const float* pb = Sb + (wn + gid) * SW;

#pragma unroll
        for (int ks = 0; ks < 2; ks++) {
            const int kw = ks * 8 + tig;
            uint32_t af[4][4], bf[4][2];
#pragma unroll
            for (int mt = 0; mt < 4; mt++) {
                af[mt][0] = __float_as_uint(pa[(mt * 16) * SW + kw]);
                af[mt][1] = __float_as_uint(pa[(mt * 16 + 8) * SW + kw]);
                af[mt][2] = __float_as_uint(pa[(mt * 16) * SW + kw + 4]);
                af[mt][3] = __float_as_uint(pa[(mt * 16 + 8) * SW + kw + 4]);
            }
#pragma unroll
            for (int nt = 0; nt < 4; nt++) {
                bf[nt][0] = __float_as_uint(pb[(nt * 8) * SW + kw]);
                bf[nt][1] = __float_as_uint(pb[(nt * 8) * SW + kw + 4]);
            }
#pragma unroll
            for (int mt = 0; mt < 4; mt++)
#pragma unroll
                for (int nt = 0; nt < 4; nt++)
                    mma_tf32(acc[mt][nt], af[mt], bf[nt]);
        }
    }

    // Epilogue: c0/c1 at (row, 2*tig), c2/c3 at (row+8, 2*tig)
#pragma unroll
    for (int mt = 0; mt < 4; mt++) {
#pragma unroll
        for (int nt = 0; nt < 4; nt++) {
            const int r = row0 + wm + mt * 16 + gid;
            const int c = col0 + wn + nt * 8 + 2 * tig;
            float o0 = acc[mt][nt][0] * scale, o1 = acc[mt][nt][1] * scale;
            float o2 = acc[mt][nt][2] * scale, o3 = acc[mt][nt][3] * scale;
            if (ROUND_OUT) {
                o0 = round_tf32f(o0); o1 = round_tf32f(o1);
                o2 = round_tf32f(o2); o3 = round_tf32f(o3);
            }
            *(float2*)(C + (size_t)r * N + c)       = make_float2(o0, o1);
            *(float2*)(C + (size_t)(r + 8) * N + c) = make_float2(o2, o3);
        }
    }
}

// ---------------------------------------------------------------------------
// Row softmax over S[SEQ, N]; one block per row. Stores tf32-rounded P.
// ---------------------------------------------------------------------------
__global__ __launch_bounds__(256)
void softmax_rows(float* __restrict__ S, int N)
{
    __shared__ float buf[SEQ];
    __shared__ float red[32];
    const int tid   = threadIdx.x;
    const int lane  = tid & 31;
    const int warp  = tid >> 5;
    const int nwarp = blockDim.x >> 5;
    float* row = S + (size_t)blockIdx.x * N;

    float lmax = -1e30f;
    for (int i = tid; i < N; i += blockDim.x) {
        float v = row[i];
        buf[i] = v;
        lmax = fmaxf(lmax, v);
    }
#pragma unroll
    for (int o = 16; o > 0; o >>= 1)
        lmax = fmaxf(lmax, __shfl_xor_sync(0xffffffffu, lmax, o));
    if (lane == 0) red[warp] = lmax;
    __syncthreads();
    if (tid < 32) {
        float v = (tid < nwarp) ? red[tid] : -1e30f;
#pragma unroll
        for (int o = 16; o > 0; o >>= 1)
            v = fmaxf(v, __shfl_xor_sync(0xffffffffu, v, o));
        red[tid] = v;
    }
    __syncthreads();
    const float rmax = red[0];
    __syncthreads();

    float lsum = 0.0f;
    for (int i = tid; i < N; i += blockDim.x) {
        float e = __expf(buf[i] - rmax);
        buf[i] = e;
        lsum += e;
    }
#pragma unroll
    for (int o = 16; o > 0; o >>= 1)
        lsum += __shfl_xor_sync(0xffffffffu, lsum, o);
    if (lane == 0) red[warp] = lsum;
    __syncthreads();
    if (tid < 32) {
        float v = (tid < nwarp) ? red[tid] : 0.0f;
#pragma unroll
        for (int o = 16; o > 0; o >>= 1)
            v += __shfl_xor_sync(0xffffffffu, v, o);
        red[tid] = v;
    }
    __syncthreads();
    const float inv = 1.0f / red[0];

    for (int i = tid; i < N; i += blockDim.x)
        row[i] = round_tf32f(buf[i] * inv);
}

// ---------------------------------------------------------------------------
extern "C" void kernel_launch(void* const* d_in, const int* in_sizes, int n_in,
                              void* d_out, int out_size)
{
    const float* x  = (const float*)d_in[0];
    const float* Wq = (const float*)d_in[1];
    const float* Wk = (const float*)d_in[2];
    const float* Wv = (const float*)d_in[3];
    float* out = (float*)d_out;

    float *xp, *wqp, *wkp, *wvp, *qp, *kp, *vp, *sp;
    cudaGetSymbolAddress((void**)&xp,  g_x);
    cudaGetSymbolAddress((void**)&wqp, g_wq);
    cudaGetSymbolAddress((void**)&wkp, g_wk);
    cudaGetSymbolAddress((void**)&wvp, g_wv);
    cudaGetSymbolAddress((void**)&qp,  g_q);
    cudaGetSymbolAddress((void**)&kp,  g_k);
    cudaGetSymbolAddress((void**)&vp,  g_v);
    cudaGetSymbolAddress((void**)&sp,  g_s);

    cudaFuncSetAttribute(gemm_mma<true>,  cudaFuncAttributeMaxDynamicSharedMemorySize, SMEM_BYTES);
    cudaFuncSetAttribute(gemm_mma<false>, cudaFuncAttributeMaxDynamicSharedMemorySize, SMEM_BYTES);

    const float scale = 1.0f / 32.0f;  // 1/sqrt(1024)

    // tf32 pre-rounding of raw inputs
    round_arr<<<(SEQ * DIM / 4 + 255) / 256, 256>>>(x,  xp,  SEQ * DIM / 4);
    round_arr<<<(DIM * DIM / 4 + 255) / 256, 256>>>(Wq, wqp, DIM * DIM / 4);
    round_arr<<<(DIM * DIM / 4 + 255) / 256, 256>>>(Wk, wkp, DIM * DIM / 4);
    round_arr<<<(DIM * DIM / 4 + 255) / 256, 256>>>(Wv, wvp, DIM * DIM / 4);

    // Q = X @ Wq^T   [4096,1024]  (rounded for S gemm)
    gemm_mma<true><<<dim3(DIM / 128, SEQ / 128), 256, SMEM_BYTES>>>(xp, wqp, qp, SEQ, DIM, DIM, 1.0f);
    // K = X @ Wk^T   [4096,1024]  (rounded)
    gemm_mma<true><<<dim3(DIM / 128, SEQ / 128), 256, SMEM_BYTES>>>(xp, wkp, kp, SEQ, DIM, DIM, 1.0f);
    // V^T = Wv @ X^T [1024,4096]  (rounded for O gemm)
    gemm_mma<true><<<dim3(SEQ / 128, DIM / 128), 256, SMEM_BYTES>>>(wvp, xp, vp, DIM, SEQ, DIM, 1.0f);
    // S = (Q @ K^T) * scale  [4096,4096]  (softmax rounds)
    gemm_mma<false><<<dim3(SEQ / 128, SEQ / 128), 256, SMEM_BYTES>>>(qp, kp, sp, SEQ, SEQ, DIM, scale);
    // softmax rows (stores tf32-rounded P)
    softmax_rows<<<SEQ, 256>>>(sp, SEQ);
    // O = P @ (V^T)^T  [4096,1024]  (final, no rounding)
    gemm_mma<false><<<dim3(DIM / 128, SEQ / 128), 256, SMEM_BYTES>>>(sp, vp, out, SEQ, DIM, SEQ, 1.0f);
}